// round 4
// baseline (speedup 1.0000x reference)
#include <cuda_runtime.h>
#include <stdint.h>

#define N 2048
#define MAXC 64             // per-column CSC capacity (col nnz ~17 mean, max <45)

// ---- device scratch (no runtime allocation) ----
__device__ int    g_row_nnz[N];
__device__ int    g_rowptr[N + 1];
__device__ int    g_col_cnt[N];          // reset by k_cols each run
__device__ int    g_csc[N * MAXC];       // packed (t << 16) | u
__device__ float4 g_xT2[N * 32];         // xT2[u*32 + b] = {x[b][ic=0..3] at node u}
__device__ float  g_outT[4 * N * 32];    // outT[j*32 + b]
__device__ unsigned int g_done;

// ============================================================================
// Kernel A (grid=2048, block=256):
//  - every block u: coalesced scan of adjacency row u, packed dual-half rank
//    scan, scatter (t,u) into per-column CSC
//  - blocks 0..63: build xT2 tile (32 u x 32 b, float4 over ic)
//  - last finishing block: prefix scan row_nnz -> rowptr
// ============================================================================
__global__ void k_build(const float* __restrict__ A,
                        const float* __restrict__ inputs) {
    __shared__ float shT[4][32][33];
    __shared__ int warp_sums[8];
    __shared__ bool s_last;

    int tid = threadIdx.x;
    int u = blockIdx.x;
    int lane = tid & 31, wid = tid >> 5;

    // ---- xT2 build (blocks 0..63): inputs(32 x 8192) -> xT2[u][b].{ic}
    if (blockIdx.x < 64) {
        int u0 = blockIdx.x * 32;
        int tx = lane, ty = wid;        // ty in 0..7
#pragma unroll
        for (int ic = 0; ic < 4; ic++)
#pragma unroll
            for (int r = 0; r < 4; r++) {
                int bb = ty + 8 * r;
                shT[ic][bb][tx] = inputs[bb * 8192 + ic * 2048 + u0 + tx];
            }
        __syncthreads();
#pragma unroll
        for (int r = 0; r < 4; r++) {
            int uu = ty + 8 * r;
            g_xT2[(u0 + uu) * 32 + tx] =
                make_float4(shT[0][tx][uu], shT[1][tx][uu],
                            shT[2][tx][uu], shT[3][tx][uu]);
        }
    }

    // ---- row scan: fully coalesced — thread reads float4 tid and tid+256
    const float4* row = (const float4*)(A + (size_t)u * N);
    float4 f0 = row[tid];          // v in [4*tid, 4*tid+4)
    float4 f1 = row[tid + 256];    // v in [1024 + 4*tid, ...)

    int v0[4], v1[4];
    int c0 = 0, c1 = 0;
    {
        int bv = 4 * tid;
        if (f0.x != 0.0f) v0[c0++] = bv + 0;
        if (f0.y != 0.0f) v0[c0++] = bv + 1;
        if (f0.z != 0.0f) v0[c0++] = bv + 2;
        if (f0.w != 0.0f) v0[c0++] = bv + 3;
        bv = 1024 + 4 * tid;
        if (f1.x != 0.0f) v1[c1++] = bv + 0;
        if (f1.y != 0.0f) v1[c1++] = bv + 1;
        if (f1.z != 0.0f) v1[c1++] = bv + 2;
        if (f1.w != 0.0f) v1[c1++] = bv + 3;
    }

    // packed dual scan: low 16 bits = half0 counts, high 16 = half1 counts
    int p = c0 | (c1 << 16);
    int inc = p;
#pragma unroll
    for (int off = 1; off < 32; off <<= 1) {
        int y = __shfl_up_sync(0xffffffffu, inc, off);
        if (lane >= off) inc += y;
    }
    if (lane == 31) warp_sums[wid] = inc;
    __syncthreads();
    if (wid == 0) {
        int w = (lane < 8) ? warp_sums[lane] : 0;
#pragma unroll
        for (int off = 1; off < 8; off <<= 1) {
            int y = __shfl_up_sync(0xffffffffu, w, off);
            if (lane >= off) w += y;
        }
        if (lane < 8) warp_sums[lane] = w;
    }
    __syncthreads();
    int excl = inc - p + ((wid > 0) ? warp_sums[wid - 1] : 0);
    int tot  = warp_sums[7];
    int base0 = excl & 0xffff;
    int tot0  = tot & 0xffff;
    int base1 = tot0 + (excl >> 16);

    for (int i = 0; i < c0; i++) {
        int v = v0[i], t = base0 + i;
        int slot = atomicAdd(&g_col_cnt[v], 1);
        if (slot < MAXC) g_csc[v * MAXC + slot] = (t << 16) | u;
    }
    for (int i = 0; i < c1; i++) {
        int v = v1[i], t = base1 + i;
        int slot = atomicAdd(&g_col_cnt[v], 1);
        if (slot < MAXC) g_csc[v * MAXC + slot] = (t << 16) | u;
    }
    if (tid == 0) g_row_nnz[u] = tot0 + (tot >> 16);

    // ---- last-block prefix scan of row_nnz -> rowptr
    __threadfence();
    if (tid == 0) {
        unsigned r = atomicAdd(&g_done, 1u);
        s_last = (r == gridDim.x - 1);
    }
    __syncthreads();
    if (!s_last) return;

    int loc[8];
    int s = 0;
    int base8 = tid * 8;
#pragma unroll
    for (int k = 0; k < 8; k++) { loc[k] = g_row_nnz[base8 + k]; s += loc[k]; }
    int inc2 = s;
#pragma unroll
    for (int off = 1; off < 32; off <<= 1) {
        int y = __shfl_up_sync(0xffffffffu, inc2, off);
        if (lane >= off) inc2 += y;
    }
    if (lane == 31) warp_sums[wid] = inc2;
    __syncthreads();
    if (wid == 0) {
        int w = (lane < 8) ? warp_sums[lane] : 0;
#pragma unroll
        for (int off = 1; off < 8; off <<= 1) {
            int y = __shfl_up_sync(0xffffffffu, w, off);
            if (lane >= off) w += y;
        }
        if (lane < 8) warp_sums[lane] = w;
    }
    __syncthreads();
    int run = inc2 - s + ((wid > 0) ? warp_sums[wid - 1] : 0);
#pragma unroll
    for (int k = 0; k < 8; k++) { g_rowptr[base8 + k] = run; run += loc[k]; }
    if (tid == 255) g_rowptr[N] = run;
    if (tid == 0) g_done = 0;
}

// ============================================================================
// Kernel B (grid=2048, block=128): one block per output column v.
//   main loop per edge: 1x LDG.128 (xT2) + 1x broadcast LDS.128 (weights)
//   + 4 independent FFMA chains.
// ============================================================================
__global__ void k_cols(const float* __restrict__ ker,
                       const float* __restrict__ bias,
                       int nnz4) {
    int v = blockIdx.x;
    int tid = threadIdx.x;
    int c = tid >> 5, b = tid & 31;

    __shared__ int s_cnt;
    __shared__ int tmp_u[MAXC], tmp_t[MAXC];
    __shared__ int s_u[MAXC], s_base[MAXC], s_rn[MAXC];
    __shared__ float4 s_w[MAXC * 4];   // [e][c] -> float4 over ic (16B aligned)

    if (tid == 0) {
        int cc = g_col_cnt[v];
        s_cnt = (cc > MAXC) ? MAXC : cc;
        g_col_cnt[v] = 0;              // reset for next replay
    }
    __syncthreads();
    int cnt = s_cnt;

    if (tid < cnt) {
        int p = g_csc[v * MAXC + tid];
        tmp_u[tid] = p & 0xffff;
        tmp_t[tid] = p >> 16;
    }
    __syncthreads();
    if (tid < cnt) {                   // deterministic rank-sort by u
        int myu = tmp_u[tid];
        int r = 0;
        for (int e = 0; e < cnt; e++) r += (tmp_u[e] < myu);
        s_u[r] = myu;
        s_base[r] = 4 * g_rowptr[myu] + tmp_t[tid];
        s_rn[r] = g_row_nnz[myu];
    }
    __syncthreads();

    // cooperative weight prefetch: s_w[e*4 + c].{ic}  (scalar float writes)
    float* s_wf = (float*)s_w;
    int total = cnt * 16;
    for (int idx = tid; idx < total; idx += 128) {
        int e = idx >> 4, w = idx & 15;
        int cc = w >> 2, ic = w & 3;
        s_wf[(e * 4 + cc) * 4 + ic] =
            __ldg(&ker[ic * nnz4 + s_base[e] + cc * s_rn[e]]);
    }
    __syncthreads();

    float a0 = 0.f, a1 = 0.f, a2 = 0.f, a3 = 0.f;
#pragma unroll 4
    for (int e = 0; e < cnt; e++) {
        float4 x4 = g_xT2[s_u[e] * 32 + b];
        float4 w4 = s_w[e * 4 + c];
        a0 += x4.x * w4.x;
        a1 += x4.y * w4.y;
        a2 += x4.z * w4.z;
        a3 += x4.w * w4.w;
    }
    int j = c * N + v;
    g_outT[(size_t)j * 32 + b] = (a0 + a1) + (a2 + a3) + __ldg(&bias[j]);
}

// ============================================================================
// Kernel C: transpose outT (8192 x 32) -> out (32 x 8192), fully coalesced.
// ============================================================================
__global__ void k_outT(float* __restrict__ out) {
    __shared__ float sh[32][33];
    int j0 = blockIdx.x * 32;
    int tx = threadIdx.x, ty = threadIdx.y;
    sh[ty][tx] = g_outT[(j0 + ty) * 32 + tx];
    __syncthreads();
    out[ty * 8192 + j0 + tx] = sh[tx][ty];
}

extern "C" void kernel_launch(void* const* d_in, const int* in_sizes, int n_in,
                              void* d_out, int out_size) {
    const float* inputs = (const float*)d_in[0];  // (32, 8192)
    const float* A      = (const float*)d_in[1];  // (2048, 2048)
    const float* ker    = (const float*)d_in[2];  // (16*NNZ,)
    const float* bias   = (const float*)d_in[3];  // (8192,)
    float* out = (float*)d_out;

    int nnz4 = in_sizes[2] / 4;   // = 4*NNZ

    k_build<<<N, 256>>>(A, inputs);
    k_cols<<<N, 128>>>(ker, bias, nnz4);
    dim3 t32x32(32, 32);
    k_outT<<<256, t32x32>>>(out);
}

// round 5
// speedup vs baseline: 1.2854x; 1.2854x over previous
#include <cuda_runtime.h>
#include <stdint.h>

#define N 2048
#define NW 64               // words per bitmap row (2048/32)
#define MAXC 64             // max in-degree bound (mean ~17)

// ---- device scratch ----
__device__ unsigned g_bm[N * NW];      // bitmap:  bit v of row u
__device__ unsigned g_bmT[N * NW];     // bitmapT: bit u of row v
__device__ int      g_P[N * NW];       // per-row exclusive word-popc prefix
__device__ int      g_row_nnz[N];
__device__ int      g_rowptr[N + 1];
__device__ float4   g_xT2[N * 32];     // xT2[u*32+b] = x[b][ic 0..3] at node u
__device__ float    g_outT[4 * N * 32];
__device__ unsigned g_done;

// ============================================================================
// K1 (grid=2048, block=256): pure-stream ballot of adjacency row u -> bitmap.
// Blocks 0..63 additionally build xT2. No atomics, no scans, no fences.
// ============================================================================
__global__ void k_bitmap(const float* __restrict__ A,
                         const float* __restrict__ inputs) {
    int tid = threadIdx.x, u = blockIdx.x;
    int lane = tid & 31, w = tid >> 5;

    const float4* row = (const float4*)(A + (size_t)u * N);
    float4 f0 = row[tid];           // elements 4*tid .. +3
    float4 f1 = row[tid + 256];     // elements 1024+4*tid .. +3

    if (blockIdx.x < 64) {          // xT2 tile (independent of row scan)
        __shared__ float shT[4][32][33];
        int u0 = blockIdx.x * 32;
#pragma unroll
        for (int ic = 0; ic < 4; ic++)
#pragma unroll
            for (int r = 0; r < 4; r++) {
                int bb = w + 8 * r;
                shT[ic][bb][lane] = inputs[bb * 8192 + ic * 2048 + u0 + lane];
            }
        __syncthreads();
#pragma unroll
        for (int r = 0; r < 4; r++) {
            int uu = w + 8 * r;
            g_xT2[(u0 + uu) * 32 + lane] =
                make_float4(shT[0][lane][uu], shT[1][lane][uu],
                            shT[2][lane][uu], shT[3][lane][uu]);
        }
    }

    unsigned m0 = (f0.x != 0.f) | ((f0.y != 0.f) << 1) |
                  ((f0.z != 0.f) << 2) | ((f0.w != 0.f) << 3);
    unsigned m1 = (f1.x != 0.f) | ((f1.y != 0.f) << 1) |
                  ((f1.z != 0.f) << 2) | ((f1.w != 0.f) << 3);

    // 8-lane subgroup OR-reduce: group g of warp w covers word 4*w+g
    unsigned grp = lane >> 3;
    unsigned sub = 0xFFu << (8 * grp);
    unsigned sh4 = (lane & 7) * 4;
    unsigned w0 = __reduce_or_sync(sub, m0 << sh4);
    unsigned w1 = __reduce_or_sync(sub, m1 << sh4);
    if ((lane & 7) == 0) {
        g_bm[u * NW + 4 * w + grp]      = w0;
        g_bm[u * NW + 32 + 4 * w + grp] = w1;
    }
}

// ============================================================================
// K2 (grid=256, block=256): structure pass over the 512KB bitmap.
//  - warp r: row u=blk*8+r -> P[u][*], row_nnz[u]
//  - warps also transpose 16 32x32-bit tiles per block -> bitmapT
//  - last block: rowptr prefix scan
// ============================================================================
__global__ void k_struct() {
    __shared__ int warp_sums[8];
    __shared__ bool s_last;
    int tid = threadIdx.x, lane = tid & 31, wid = tid >> 5;

    // ---- per-row popc prefix
    {
        int u = blockIdx.x * 8 + wid;
        unsigned b0 = g_bm[u * NW + lane];
        unsigned b1 = g_bm[u * NW + 32 + lane];
        int p = __popc(b0) | (__popc(b1) << 16);
        int inc = p;
#pragma unroll
        for (int off = 1; off < 32; off <<= 1) {
            int y = __shfl_up_sync(0xffffffffu, inc, off);
            if (lane >= off) inc += y;
        }
        int tot = __shfl_sync(0xffffffffu, inc, 31);
        int excl = inc - p;
        int tot0 = tot & 0xffff;
        g_P[u * NW + lane]      = excl & 0xffff;
        g_P[u * NW + 32 + lane] = tot0 + (excl >> 16);
        if (lane == 0) g_row_nnz[u] = tot0 + (tot >> 16);
    }

    // ---- bit transpose: 4096 tiles of 32x32 bits; 2 tiles per warp
#pragma unroll
    for (int q = 0; q < 2; q++) {
        int t = (blockIdx.x * 8 + wid) * 2 + q;
        int i = t >> 6, j = t & 63;          // rows 32i.., word j
        unsigned x = g_bm[(32 * i + lane) * NW + j];
        unsigned m = 0x0000FFFFu;
#pragma unroll
        for (int s = 16; s >= 1; s >>= 1) {
            unsigned y = __shfl_xor_sync(0xffffffffu, x, s);
            x = (lane & s) ? ((x & ~m) | ((y >> s) & m))
                           : ((x & m) | ((y << s) & ~m));
            m ^= (m << (s >> 1));            // 0xFFFF->0xFF00FF? fixed below
            if (s == 16) m = 0x00FF00FFu;
            else if (s == 8) m = 0x0F0F0F0Fu;
            else if (s == 4) m = 0x33333333u;
            else if (s == 2) m = 0x55555555u;
        }
        g_bmT[(32 * j + lane) * NW + i] = x;
    }

    // ---- last block: rowptr scan
    __threadfence();
    if (tid == 0) {
        unsigned r = atomicAdd(&g_done, 1u);
        s_last = (r == gridDim.x - 1);
    }
    __syncthreads();
    if (!s_last) return;

    int loc[8], s = 0, base8 = tid * 8;
#pragma unroll
    for (int k = 0; k < 8; k++) { loc[k] = g_row_nnz[base8 + k]; s += loc[k]; }
    int inc2 = s;
#pragma unroll
    for (int off = 1; off < 32; off <<= 1) {
        int y = __shfl_up_sync(0xffffffffu, inc2, off);
        if (lane >= off) inc2 += y;
    }
    if (lane == 31) warp_sums[wid] = inc2;
    __syncthreads();
    if (wid == 0) {
        int wv = (lane < 8) ? warp_sums[lane] : 0;
#pragma unroll
        for (int off = 1; off < 8; off <<= 1) {
            int y = __shfl_up_sync(0xffffffffu, wv, off);
            if (lane >= off) wv += y;
        }
        if (lane < 8) warp_sums[lane] = wv;
    }
    __syncthreads();
    int run = inc2 - s + ((wid > 0) ? warp_sums[wid - 1] : 0);
#pragma unroll
    for (int k = 0; k < 8; k++) { g_rowptr[base8 + k] = run; run += loc[k]; }
    if (tid == 255) g_rowptr[N] = run;
    if (tid == 0) g_done = 0;
}

// ============================================================================
// K3 (grid=2048, block=128): one block per output column v.
//  Edge list from bitmapT (already sorted by u); rank t from P + popc.
// ============================================================================
__global__ void k_cols(const float* __restrict__ ker,
                       const float* __restrict__ bias,
                       int nnz4) {
    int v = blockIdx.x;
    int tid = threadIdx.x;
    int c = tid >> 5, b = tid & 31;
    int lane = tid & 31, wid = tid >> 5;

    __shared__ int s_u[MAXC], s_base[MAXC], s_rn[MAXC];
    __shared__ float4 s_w[MAXC * 4];   // [e][c] float4 over ic
    __shared__ int s_wsum;
    __shared__ int s_cnt;

    // ---- extract column v's incoming edges from bitmapT row v (64 words)
    unsigned word = 0;
    int pc = 0;
    if (tid < 64) { word = g_bmT[v * NW + tid]; pc = __popc(word); }
    int inc = pc;
#pragma unroll
    for (int off = 1; off < 32; off <<= 1) {
        int y = __shfl_up_sync(0xffffffffu, inc, off);
        if (lane >= off) inc += y;
    }
    if (wid == 0 && lane == 31) s_wsum = inc;
    __syncthreads();
    int excl = inc - pc + ((wid == 1) ? s_wsum : 0);
    if (tid < 64) {
        unsigned ww = word;
        int e = excl;
        while (ww) {
            int bit = __ffs(ww) - 1;
            ww &= ww - 1;
            if (e < MAXC) s_u[e] = tid * 32 + bit;
            e++;
        }
    }
    if (tid == 96) { /* nothing */ }
    if (wid == 1 && lane == 31) s_cnt = excl + pc;
    __syncthreads();
    int cnt = s_cnt;
    if (cnt > MAXC) cnt = MAXC;

    // ---- per-edge metadata: t-rank, rowptr, row_nnz
    if (tid < cnt) {
        int u = s_u[tid];
        int wv = v >> 5, bt = v & 31;
        unsigned rw = g_bm[u * NW + wv];
        int t = g_P[u * NW + wv] + __popc(rw & ((1u << bt) - 1u));
        s_base[tid] = 4 * g_rowptr[u] + t;
        s_rn[tid] = g_row_nnz[u];
    }
    __syncthreads();

    // ---- cooperative weight prefetch: s_w[e*4+c].{ic}
    float* s_wf = (float*)s_w;
    int total = cnt * 16;
    for (int idx = tid; idx < total; idx += 128) {
        int e = idx >> 4, q = idx & 15;
        int cc = q >> 2, ic = q & 3;
        s_wf[(e * 4 + cc) * 4 + ic] =
            __ldg(&ker[ic * nnz4 + s_base[e] + cc * s_rn[e]]);
    }
    __syncthreads();

    float a0 = 0.f, a1 = 0.f, a2 = 0.f, a3 = 0.f;
#pragma unroll 4
    for (int e = 0; e < cnt; e++) {
        float4 x4 = g_xT2[s_u[e] * 32 + b];
        float4 w4 = s_w[e * 4 + c];
        a0 += x4.x * w4.x;
        a1 += x4.y * w4.y;
        a2 += x4.z * w4.z;
        a3 += x4.w * w4.w;
    }
    int j = c * N + v;
    g_outT[(size_t)j * 32 + b] = (a0 + a1) + (a2 + a3) + __ldg(&bias[j]);
}

// ============================================================================
// K4: transpose outT (8192 x 32) -> out (32 x 8192)
// ============================================================================
__global__ void k_outT(float* __restrict__ out) {
    __shared__ float sh[32][33];
    int j0 = blockIdx.x * 32;
    int tx = threadIdx.x, ty = threadIdx.y;
    sh[ty][tx] = g_outT[(j0 + ty) * 32 + tx];
    __syncthreads();
    out[ty * 8192 + j0 + tx] = sh[tx][ty];
}

extern "C" void kernel_launch(void* const* d_in, const int* in_sizes, int n_in,
                              void* d_out, int out_size) {
    const float* inputs = (const float*)d_in[0];  // (32, 8192)
    const float* A      = (const float*)d_in[1];  // (2048, 2048)
    const float* ker    = (const float*)d_in[2];  // (16*NNZ,)
    const float* bias   = (const float*)d_in[3];  // (8192,)
    float* out = (float*)d_out;

    int nnz4 = in_sizes[2] / 4;   // = 4*NNZ

    k_bitmap<<<N, 256>>>(A, inputs);
    k_struct<<<256, 256>>>();
    k_cols<<<N, 128>>>(ker, bias, nnz4);
    dim3 t32x32(32, 32);
    k_outT<<<256, t32x32>>>(out);
}